// round 16
// baseline (speedup 1.0000x reference)
#include <cuda_runtime.h>
#include <stdint.h>

#define NP     65536
#define NA     1024
#define NMAX   512
#define GRID   100
#define CELLS  (GRID * GRID)
#define CAP    48          // max pts/cell; lambda=6.55 => P(>48) < 1e-20
#define TPB    256         // threads per anchor block

// Scratch (allocation-free rule: __device__ globals). Zero-initialized at load.
__device__ int      g_cnt2[2 * CELLS];   // double-buffered counters; stale side is ALL ZERO
__device__ int      g_epoch;             // which buffer k_bin fills this launch
__device__ unsigned g_done;              // monotonic k_bin completion counter (never reset)
__device__ float4   g_bin[CELLS * CAP];  // packed (x,y,z,(float)pointIdx); idx<=65535 exact in f32

static __device__ __forceinline__ int cell_of(float x, float y) {
    int gx = (int)floorf(x);          // cell size = 1.0
    int gy = (int)floorf(y);
    gx = min(GRID - 1, max(0, gx));
    gy = min(GRID - 1, max(0, gy));
    return gy * GRID + gx;
}

// 1 point per thread (65536 threads, 256 blocks):
//  - zero the OTHER count buffer (for next launch; nothing reads it now)
//  - zero this thread's 96-byte share of the output (6 coalesced STG.128)
//  - bin the point into buf[e]
//  - PDL trigger (per-thread, after all k_anchor-visible writes)
//  - last-finishing block flips the epoch (read only by NEXT launch).
__global__ void k_bin(const float* __restrict__ pts, float4* __restrict__ out4) {
    int e = *((volatile int*)&g_epoch);
    int* cnt  = g_cnt2 + e * CELLS;
    int* cntn = g_cnt2 + (1 - e) * CELLS;

    int p = blockIdx.x * blockDim.x + threadIdx.x;
    if (p < CELLS) cntn[p] = 0;                     // restore all-zero invariant

    float x = __ldg(&pts[p * 3 + 0]);
    float y = __ldg(&pts[p * 3 + 1]);
    float z = __ldg(&pts[p * 3 + 2]);

    float4 z4 = make_float4(0.f, 0.f, 0.f, 0.f);
#pragma unroll
    for (int k = 0; k < 6; k++) out4[k * NP + p] = z4;   // zero output region

    int c = cell_of(x, y);
    int pos = atomicAdd(&cnt[c], 1);
    if (pos < CAP) g_bin[c * CAP + pos] = make_float4(x, y, z, (float)p);

    // All of this thread's k_anchor-visible writes are done: allow dependents.
    cudaTriggerProgrammaticLaunchCompletion();

    __syncthreads();
    if (threadIdx.x == 0) {
        __threadfence();
        unsigned old = atomicAdd(&g_done, 1u);
        if ((old % 256u) == 255u) {                 // 256 blocks per launch
            g_epoch = 1 - e;                        // for NEXT launch only
            __threadfence();
        }
    }
}

// One block per anchor. Launched with programmatic stream serialization:
// box setup overlaps k_bin; cudaGridDependencySynchronize gates data reads.
__global__ void __launch_bounds__(TPB, 7) k_anchor(
    const float* __restrict__ anch,
    float* __restrict__ out,
    float* __restrict__ counts_out)
{
    int a = blockIdx.x;
    int tid = threadIdx.x;
    int lane = tid & 31;

    // ---- Pre-wait: everything independent of k_bin's writes ----
    const float2* arow = (const float2*)(anch + a * 6);
    float2 f01 = __ldg(&arow[0]);   // cx, cy
    float2 f23 = __ldg(&arow[1]);   // cz, w
    float2 f45 = __ldg(&arow[2]);   // l, h
    float cx = f01.x, cy = f01.y;
    float w = f23.y, l = f45.x, h = f45.y;
    float hw = w * 0.5f, hl = l * 0.5f;
    float x0 = cx - hw, x1 = cx + hw;
    float y0 = cy - hl, y1 = cy + hl;

    int gx0 = max(0, (int)floorf(x0));
    int gx1 = min(GRID - 1, (int)floorf(x1));
    int gy0 = max(0, (int)floorf(y0));
    int gy1 = min(GRID - 1, (int)floorf(y1));
    int ncx = gx1 - gx0 + 1;
    int ncy = gy1 - gy0 + 1;
    int ncells = ncx * ncy;   // <= 36 (w,l <= 5, cell = 1.0)

    __shared__ int           s_base[40];      // g_bin base per covered cell
    __shared__ int           s_ccnt[40];
    __shared__ int           s_off[40];       // exclusive offset per cell
    __shared__ int           s_total;
    __shared__ unsigned char s_cid[36 * CAP]; // candidate -> covered-cell id
    __shared__ float         s_key[NMAX];     // point index as float (exact)
    __shared__ float         s_px[NMAX], s_py[NMAX], s_pz[NMAX];
    __shared__ int           s_count;

    if (tid == 0) s_count = 0;

    int my_cell = 0;
    if (tid < ncells) {
        int cgx = gx0 + (tid % ncx);
        int cgy = gy0 + (tid / ncx);
        my_cell = cgy * GRID + cgx;
        s_base[tid] = my_cell * CAP;
    }

    // ---- Wait for the primary grid's (k_bin's) writes ----
    cudaGridDependencySynchronize();

    if (tid < ncells) {
        // live + zero = live; both loads issue in parallel (independent).
        int ca = __ldg(&g_cnt2[my_cell]);
        int cb = __ldg(&g_cnt2[CELLS + my_cell]);
        s_ccnt[tid] = min(ca + cb, CAP);
    }
    __syncthreads();                                   // (1)

    if (tid < ncells) {
        int off = 0;
        for (int j = 0; j < tid; j++) off += s_ccnt[j];
        s_off[tid] = off;
        int cc = s_ccnt[tid];
        for (int k = 0; k < cc; k++) s_cid[off + k] = (unsigned char)tid;
        if (tid == ncells - 1) s_total = off + cc;
    }
    __syncthreads();                                   // (2)

    int total = s_total;

    // Phase A: test candidates (usually one pass: total ~230 < 256), warp-
    // aggregated compaction of key AND coords into shared (order-free).
    for (int i0 = 0; i0 < total; i0 += TPB) {
        int i = i0 + tid;
        bool hit = false;
        float4 r = make_float4(0.f, 0.f, 0.f, 0.f);
        if (i < total) {
            int j = (int)s_cid[i];
            r = __ldg(&g_bin[s_base[j] + (i - s_off[j])]);
            hit = (r.x >= x0 && r.x <= x1 && r.y >= y0 && r.y <= y1 &&
                   r.z >= 0.0f && r.z <= h);
        }
        unsigned bal = __ballot_sync(0xFFFFFFFFu, hit);
        int nb = __popc(bal);
        int base = 0;
        if (lane == 0 && nb) base = atomicAdd(&s_count, nb);
        base = __shfl_sync(0xFFFFFFFFu, base, 0);
        if (hit) {
            int pos = base + __popc(bal & ((1u << lane) - 1u));
            if (pos < NMAX) {
                s_key[pos] = r.w;
                s_px[pos] = r.x; s_py[pos] = r.y; s_pz[pos] = r.z;
            }
        }
    }
    __syncthreads();                                   // (3)

    int cnt = s_count;
    int m = min(cnt, NMAX);
    float* outa = out + (size_t)a * NMAX * 3;

    // Rank-by-counting (broadcast LDS) + direct ranked store. Tail [3m,1536)
    // was zeroed by k_bin; only the 3m live floats are written here.
    for (int s = tid; s < m; s += TPB) {
        float key = s_key[s];
        int r = 0;
        int j = 0;
        for (; j + 4 <= m; j += 4) {
            r += (s_key[j + 0] < key);
            r += (s_key[j + 1] < key);
            r += (s_key[j + 2] < key);
            r += (s_key[j + 3] < key);
        }
        for (; j < m; j++) r += (s_key[j] < key);
        outa[r * 3 + 0] = s_px[s] - cx;
        outa[r * 3 + 1] = s_py[s] - cy;
        outa[r * 3 + 2] = s_pz[s];
    }
    if (tid == 0) counts_out[a] = (float)cnt;
}

extern "C" void kernel_launch(void* const* d_in, const int* in_sizes, int n_in,
                              void* d_out, int out_size) {
    const float* pts  = (const float*)d_in[0];   // (65536, 3) f32
    const float* anch = (const float*)d_in[1];   // (1024, 6)  f32
    float* out = (float*)d_out;                  // 1024*512*3 f32, then 1024 counts
    float* counts_out = out + (size_t)NA * NMAX * 3;

    k_bin<<<NP / 256, 256>>>(pts, (float4*)out);

    // k_anchor with programmatic stream serialization (PDL): its launch +
    // prologue overlap k_bin; cudaGridDependencySynchronize gates data reads.
    cudaLaunchConfig_t cfg = {};
    cfg.gridDim  = dim3(NA, 1, 1);
    cfg.blockDim = dim3(TPB, 1, 1);
    cfg.dynamicSmemBytes = 0;
    cudaLaunchAttribute attrs[1];
    attrs[0].id = cudaLaunchAttributeProgrammaticStreamSerialization;
    attrs[0].val.programmaticStreamSerializationAllowed = 1;
    cfg.attrs = attrs;
    cfg.numAttrs = 1;
    cudaLaunchKernelEx(&cfg, k_anchor, anch, out, counts_out);
}